// round 1
// baseline (speedup 1.0000x reference)
#include <cuda_runtime.h>

#define XS 128
#define BATCH 8
#define NPTS 262144                      // 2^18 points per batch
#define GRID_ELEMS (BATCH * XS * XS * XS)   // 16,777,216 floats = 67 MB

__device__ float g_grid[GRID_ELEMS];

// ---------------------------------------------------------------------------
// Kernel 1: zero the grid (float4 stores) + zero the 16 output accumulators
// ---------------------------------------------------------------------------
__global__ void zero_kernel(float* __restrict__ d_out, int out_size) {
    int t = blockIdx.x * blockDim.x + threadIdx.x;   // 0 .. 4194303
    float4 z = make_float4(0.f, 0.f, 0.f, 0.f);
    reinterpret_cast<float4*>(g_grid)[t] = z;
    if (t < 16 && t < out_size) d_out[t] = 0.f;
}

// ---------------------------------------------------------------------------
// Kernel 2: scatter-add point values into the grid
// ---------------------------------------------------------------------------
__global__ void scatter_kernel(const int* __restrict__ indices,
                               const float* __restrict__ values) {
    int t = blockIdx.x * blockDim.x + threadIdx.x;   // 0 .. 2097151
    int b = t >> 18;                                  // t / NPTS
    int base = 3 * t;
    int x = indices[base + 0];
    int y = indices[base + 1];
    int z = indices[base + 2];
    int gidx = (((b << 7) | x) << 14) | (y << 7) | z; // ((b*128+x)*128+y)*128+z
    atomicAdd(&g_grid[gidx], values[t]);              // RED.F32, no return
}

// ---------------------------------------------------------------------------
// Kernel 3: fused TV + MSE reduction. One thread = 4 voxels along z (float4).
// 2048 blocks per batch, block never straddles batches.
// ---------------------------------------------------------------------------
__global__ void reduce_kernel(float* __restrict__ d_out) {
    int b    = blockIdx.x >> 11;                         // 2048 blocks / batch
    int tloc = ((blockIdx.x & 2047) << 8) + threadIdx.x; // 0 .. 524287
    int k4 = tloc & 31;            // which float4 along z (z = 4*k4 .. 4*k4+3)
    int j  = (tloc >> 5) & 127;
    int i  = tloc >> 12;

    const float* base = g_grid + ((size_t)b << 21) + (i << 14) + (j << 7) + (k4 << 2);
    float4 g = *reinterpret_cast<const float4*>(base);

    float tv = 0.f, mse = 0.f;
    float d;

    // z-axis diffs internal to the float4
    d = g.y - g.x; tv += fabsf(d); mse += d * d;
    d = g.z - g.y; tv += fabsf(d); mse += d * d;
    d = g.w - g.z; tv += fabsf(d); mse += d * d;
    // z-axis seam to next float4
    if (k4 < 31) {
        d = base[4] - g.w; tv += fabsf(d); mse += d * d;
    }
    // y-axis diffs (row j+1, 512 B away)
    if (j < 127) {
        float4 n = *reinterpret_cast<const float4*>(base + 128);
        d = n.x - g.x; tv += fabsf(d); mse += d * d;
        d = n.y - g.y; tv += fabsf(d); mse += d * d;
        d = n.z - g.z; tv += fabsf(d); mse += d * d;
        d = n.w - g.w; tv += fabsf(d); mse += d * d;
    }
    // x-axis diffs (plane i+1, 64 KB away — L2 hit)
    if (i < 127) {
        float4 n = *reinterpret_cast<const float4*>(base + 16384);
        d = n.x - g.x; tv += fabsf(d); mse += d * d;
        d = n.y - g.y; tv += fabsf(d); mse += d * d;
        d = n.z - g.z; tv += fabsf(d); mse += d * d;
        d = n.w - g.w; tv += fabsf(d); mse += d * d;
    }

    // warp reduce
    #pragma unroll
    for (int o = 16; o; o >>= 1) {
        tv  += __shfl_down_sync(0xffffffffu, tv,  o);
        mse += __shfl_down_sync(0xffffffffu, mse, o);
    }
    __shared__ float stv[8], smse[8];
    int lane = threadIdx.x & 31, w = threadIdx.x >> 5;
    if (lane == 0) { stv[w] = tv; smse[w] = mse; }
    __syncthreads();
    if (threadIdx.x == 0) {
        float TV = 0.f, MS = 0.f;
        #pragma unroll
        for (int q = 0; q < 8; q++) { TV += stv[q]; MS += smse[q]; }
        const float inv_tv  = 1.f / 2097152.f;           // xsize^3
        const float inv_mse = 1.f / 32512.f;             // 2*128*128 - 2*128
        atomicAdd(&d_out[b],     TV * inv_tv);
        atomicAdd(&d_out[8 + b], MS * inv_mse);
    }
}

// ---------------------------------------------------------------------------
extern "C" void kernel_launch(void* const* d_in, const int* in_sizes, int n_in,
                              void* d_out, int out_size) {
    const int*   indices = (const int*)d_in[0];    // [B, N, 3] int32
    const float* values  = (const float*)d_in[1];  // [B, N] float32
    float* out = (float*)d_out;                    // tv[8] ++ mse[8]

    // 16,777,216 floats / 4 per float4 / 256 threads = 16384 blocks
    zero_kernel<<<16384, 256>>>(out, out_size);
    // 2,097,152 points / 256 = 8192 blocks
    scatter_kernel<<<8192, 256>>>(indices, values);
    // 4,194,304 float4-threads / 256 = 16384 blocks (2048 per batch)
    reduce_kernel<<<16384, 256>>>(out);
}

// round 2
// speedup vs baseline: 1.5655x; 1.5655x over previous
#include <cuda_runtime.h>

#define XS 128
#define BATCH 8
#define GRID_ELEMS (BATCH * XS * XS * XS)   // 16,777,216 floats = 67 MB (fits L2)

__device__ float g_grid[GRID_ELEMS];

// ---------------------------------------------------------------------------
// Kernel 1: zero the grid (2x float4 per thread) + zero the 16 output accums
// ---------------------------------------------------------------------------
__global__ void zero_kernel(float* __restrict__ d_out, int out_size) {
    int t = blockIdx.x * blockDim.x + threadIdx.x;   // 0 .. 2097151
    float4 z = make_float4(0.f, 0.f, 0.f, 0.f);
    float4* g4 = reinterpret_cast<float4*>(g_grid);
    g4[t]           = z;
    g4[t + 2097152] = z;
    if (t < 16 && t < out_size) d_out[t] = 0.f;
}

// ---------------------------------------------------------------------------
// Kernel 2: scatter-add, 4 points per thread.
// Layout: 12 ints per 4 points -> 3x int4, values -> 1x float4.
// __ldcs: stream indices/values through L2 without evicting the grid.
// ---------------------------------------------------------------------------
__global__ void scatter_kernel(const int4* __restrict__ idx4,
                               const float4* __restrict__ val4) {
    int t = blockIdx.x * blockDim.x + threadIdx.x;   // 0 .. 524287
    int b = t >> 16;                                 // 65536 threads per batch
    int4 a = __ldcs(idx4 + 3 * t);                   // x0 y0 z0 x1
    int4 c = __ldcs(idx4 + 3 * t + 1);               // y1 z1 x2 y2
    int4 e = __ldcs(idx4 + 3 * t + 2);               // z2 x3 y3 z3
    float4 v = __ldcs(val4 + t);
    float* gb = g_grid + (b << 21);
    atomicAdd(gb + ((a.x << 14) | (a.y << 7) | a.z), v.x);
    atomicAdd(gb + ((a.w << 14) | (c.x << 7) | c.y), v.y);
    atomicAdd(gb + ((c.z << 14) | (c.w << 7) | e.x), v.z);
    atomicAdd(gb + ((e.y << 14) | (e.z << 7) | e.w), v.w);
}

// ---------------------------------------------------------------------------
// Kernel 3: fused TV + MSE reduction, minimal L2 traffic.
// Block = 512 threads = 16 j-rows x 32 z-quads (full z). Loops over 16 planes
// of i (+1 halo plane). x-diffs from a register (prev plane), y- and z-seam
// diffs from double-buffered shared memory. Each voxel read ~1.12x total.
// Grid: 8 batches x 8 j-chunks x 8 i-chunks = 512 blocks.
// ---------------------------------------------------------------------------
__global__ void reduce_kernel(float* __restrict__ d_out) {
    __shared__ float4 sb[2][512];
    __shared__ float stv[16], smse[16];

    int tid = threadIdx.x;
    int k4  = tid & 31;          // z quad: z = 4*k4 .. 4*k4+3
    int jl  = tid >> 5;          // 0..15 local j
    int bx  = blockIdx.x;
    int b   = bx >> 6;
    int jc  = (bx >> 3) & 7;
    int ic  = bx & 7;
    int i0  = ic << 4;
    int j0  = jc << 4;

    const float* gb   = g_grid + ((size_t)b << 21);
    const float* colp = gb + ((j0 + jl) << 7) + (k4 << 2);

    float tv = 0.f, mse = 0.f;
    float4 prev = make_float4(0.f, 0.f, 0.f, 0.f);

    #pragma unroll 1
    for (int ii = 0; ii <= 16; ii++) {
        int i = i0 + ii;
        if (i > 127) break;                          // uniform across block
        const float* p = colp + (i << 14);
        float4 g = *reinterpret_cast<const float4*>(p);

        if (ii > 0) {                                // x-diffs (pairs i-1, i)
            float d;
            d = g.x - prev.x; tv += fabsf(d); mse = fmaf(d, d, mse);
            d = g.y - prev.y; tv += fabsf(d); mse = fmaf(d, d, mse);
            d = g.z - prev.z; tv += fabsf(d); mse = fmaf(d, d, mse);
            d = g.w - prev.w; tv += fabsf(d); mse = fmaf(d, d, mse);
        }
        prev = g;

        if (ii < 16) {                               // owned plane: y + z diffs
            float4* s = sb[ii & 1];
            s[tid] = g;

            float4 yn = make_float4(0.f, 0.f, 0.f, 0.f);
            bool top = (jl == 15);
            bool have_y = true;
            if (top) {
                if (j0 + 16 <= 127)                  // halo row from next chunk
                    yn = *reinterpret_cast<const float4*>(p + 128);
                else
                    have_y = false;                  // j = 127 global edge
            }
            __syncthreads();

            float d;
            // z-diffs internal to the quad
            d = g.y - g.x; tv += fabsf(d); mse = fmaf(d, d, mse);
            d = g.z - g.y; tv += fabsf(d); mse = fmaf(d, d, mse);
            d = g.w - g.z; tv += fabsf(d); mse = fmaf(d, d, mse);
            // z-seam to next quad via shared
            if (k4 < 31) {
                d = s[tid + 1].x - g.w; tv += fabsf(d); mse = fmaf(d, d, mse);
            }
            // y-diffs: row jl+1 from shared, or halo row for jl==15
            if (!top) yn = s[tid + 32];
            if (!top || have_y) {
                d = yn.x - g.x; tv += fabsf(d); mse = fmaf(d, d, mse);
                d = yn.y - g.y; tv += fabsf(d); mse = fmaf(d, d, mse);
                d = yn.z - g.z; tv += fabsf(d); mse = fmaf(d, d, mse);
                d = yn.w - g.w; tv += fabsf(d); mse = fmaf(d, d, mse);
            }
        }
    }

    // block reduction: warp shuffle -> shared -> single atomicAdd
    #pragma unroll
    for (int o = 16; o; o >>= 1) {
        tv  += __shfl_down_sync(0xffffffffu, tv,  o);
        mse += __shfl_down_sync(0xffffffffu, mse, o);
    }
    int lane = tid & 31, w = tid >> 5;
    if (lane == 0) { stv[w] = tv; smse[w] = mse; }
    __syncthreads();
    if (tid == 0) {
        float TV = 0.f, MS = 0.f;
        #pragma unroll
        for (int q = 0; q < 16; q++) { TV += stv[q]; MS += smse[q]; }
        const float inv_tv  = 1.f / 2097152.f;       // xsize^3
        const float inv_mse = 1.f / 32512.f;         // 2*128*128 - 2*128
        atomicAdd(&d_out[b],     TV * inv_tv);
        atomicAdd(&d_out[8 + b], MS * inv_mse);
    }
}

// ---------------------------------------------------------------------------
extern "C" void kernel_launch(void* const* d_in, const int* in_sizes, int n_in,
                              void* d_out, int out_size) {
    const int4*   idx4 = (const int4*)d_in[0];    // [B, N, 3] int32
    const float4* val4 = (const float4*)d_in[1];  // [B, N] float32
    float* out = (float*)d_out;                   // tv[8] ++ mse[8]

    zero_kernel<<<2048, 1024>>>(out, out_size);   // 2M threads x 2 float4
    scatter_kernel<<<2048, 256>>>(idx4, val4);    // 524288 threads x 4 points
    reduce_kernel<<<512, 512>>>(out);             // 8b x 8j x 8i slabs
}